// round 9
// baseline (speedup 1.0000x reference)
#include <cuda_runtime.h>
#include <cuda_fp16.h>
#include <cstdint>

// ============================================================
// Fused 4-layer MLP via mma.sync m16n8k16 f16 (fp32 accum).
//   out = relu( ((relu(x@W0^T)) @ W1^T @ W2^T) @ W3^T )
// Each warp carries 2x16 rows through all layers in registers.
// cp.async double-buffered x staging; XOR-swizzled SMEM.
// B fragments packed as uint4 in SMEM: 1 LDS.128 -> 4 MMAs.
// R8: __launch_bounds__(128,4) -> 4 CTAs/SM (16 warps) for issue supply.
// ============================================================

#define THREADS 128          // 4 warps/CTA
#define ROWS_PER_WARP 32     // 2 x m16 subtiles
#define TILE_ROWS 128        // 4 warps x 32 rows
#define CTAS_PER_SM 4

// dynamic SMEM layout (bytes)
#define SM_X0   0            // 128 rows x 128B (16 KB)
#define SM_X1   16384
#define SM_W0P  32768        // 256 uint4 (4 KB)
#define SM_W1P  36864        // 512 uint4 (8 KB)
#define SM_W2P  45056        // 512 uint4 (8 KB)
#define SM_W3P  53248        // 128 uint4 (2 KB)
#define SM_TOTAL 55296

static __device__ __forceinline__ uint32_t f22h2(float lo, float hi) {
    __half2 h = __floats2half2_rn(lo, hi);   // lo -> .x (low half)
    return *reinterpret_cast<uint32_t*>(&h);
}

static __device__ __forceinline__ void mma16(float c[4], const uint32_t a[4],
                                             uint32_t b0, uint32_t b1) {
    asm volatile(
        "mma.sync.aligned.m16n8k16.row.col.f32.f16.f16.f32 "
        "{%0,%1,%2,%3}, {%4,%5,%6,%7}, {%8,%9}, {%0,%1,%2,%3};"
        : "+f"(c[0]), "+f"(c[1]), "+f"(c[2]), "+f"(c[3])
        : "r"(a[0]), "r"(a[1]), "r"(a[2]), "r"(a[3]), "r"(b0), "r"(b1));
}

// relu on packed f16x2
static __device__ __forceinline__ uint32_t hmax0(uint32_t v) {
    __half2 h = *reinterpret_cast<__half2*>(&v);
    __half2 z = __float2half2_rn(0.f);
    __half2 r = __hmax2(h, z);
    return *reinterpret_cast<uint32_t*>(&r);
}

__global__ void __launch_bounds__(THREADS, CTAS_PER_SM)
ffmlp_kernel(const float* __restrict__ x,
             const float* __restrict__ W0, const float* __restrict__ W1,
             const float* __restrict__ W2, const float* __restrict__ W3,
             float* __restrict__ out, int Brows) {
    extern __shared__ char sm[];
    uint4* w0p = reinterpret_cast<uint4*>(sm + SM_W0P);
    uint4* w1p = reinterpret_cast<uint4*>(sm + SM_W1P);
    uint4* w2p = reinterpret_cast<uint4*>(sm + SM_W2P);
    uint4* w3p = reinterpret_cast<uint4*>(sm + SM_W3P);

    const int tid = threadIdx.x;

    // ---- stage weights (fp16 pairs) ----
    // L0 with x-load permutation sigma0 (matches xa unpack below)
    for (int i = tid; i < 256; i += THREADS) {
        int u = i >> 7, j2 = (i >> 5) & 3, r = (i >> 2) & 7, m = i & 3;
        int n0 = 16 * j2 + r, n1 = n0 + 8;
        int k = 8 * m + 4 * u;
        const float* p0 = W0 + n0 * 32 + k;
        const float* p1 = W0 + n1 * 32 + k;
        uint4 v;
        v.x = f22h2(__ldg(p0 + 0), __ldg(p0 + 1));
        v.y = f22h2(__ldg(p0 + 2), __ldg(p0 + 3));
        v.z = f22h2(__ldg(p1 + 0), __ldg(p1 + 1));
        v.w = f22h2(__ldg(p1 + 2), __ldg(p1 + 3));
        w0p[i] = v;
    }
    // L1/L2: natural layout (C->A chain needs no permutation for f16 pairs)
    for (int i = tid; i < 512; i += THREADS) {
        int u = i >> 7, j2 = (i >> 5) & 3, r = (i >> 2) & 7, m = i & 3;
        int n0 = 16 * j2 + r, n1 = n0 + 8;
        int k0 = 16 * u + 2 * m;
        uint4 v;
        v.x = f22h2(__ldg(W1 + n0 * 64 + k0),     __ldg(W1 + n0 * 64 + k0 + 1));
        v.y = f22h2(__ldg(W1 + n0 * 64 + k0 + 8), __ldg(W1 + n0 * 64 + k0 + 9));
        v.z = f22h2(__ldg(W1 + n1 * 64 + k0),     __ldg(W1 + n1 * 64 + k0 + 1));
        v.w = f22h2(__ldg(W1 + n1 * 64 + k0 + 8), __ldg(W1 + n1 * 64 + k0 + 9));
        w1p[i] = v;
        v.x = f22h2(__ldg(W2 + n0 * 64 + k0),     __ldg(W2 + n0 * 64 + k0 + 1));
        v.y = f22h2(__ldg(W2 + n0 * 64 + k0 + 8), __ldg(W2 + n0 * 64 + k0 + 9));
        v.z = f22h2(__ldg(W2 + n1 * 64 + k0),     __ldg(W2 + n1 * 64 + k0 + 1));
        v.w = f22h2(__ldg(W2 + n1 * 64 + k0 + 8), __ldg(W2 + n1 * 64 + k0 + 9));
        w2p[i] = v;
    }
    // L3 with N-permutation so each thread's C covers 4 adjacent out cols:
    // block j, frag row r -> physical col 4*(r>>1) + 2*j + (r&1)
    for (int i = tid; i < 128; i += THREADS) {
        int u = i >> 5, r = (i >> 2) & 7, m = i & 3;
        int n0 = 4 * (r >> 1) + (r & 1);   // block 0
        int n1 = n0 + 2;                   // block 1
        int k0 = 16 * u + 2 * m;
        uint4 v;
        v.x = f22h2(__ldg(W3 + n0 * 64 + k0),     __ldg(W3 + n0 * 64 + k0 + 1));
        v.y = f22h2(__ldg(W3 + n0 * 64 + k0 + 8), __ldg(W3 + n0 * 64 + k0 + 9));
        v.z = f22h2(__ldg(W3 + n1 * 64 + k0),     __ldg(W3 + n1 * 64 + k0 + 1));
        v.w = f22h2(__ldg(W3 + n1 * 64 + k0 + 8), __ldg(W3 + n1 * 64 + k0 + 9));
        w3p[i] = v;
    }

    const int wid  = tid >> 5;
    const int lane = tid & 31;
    const int r = lane >> 2;      // group id (row within 8)
    const int m = lane & 3;       // thread-in-group
    const int lidx = r * 4 + m;   // packed (r,m) index

    const int ntiles = Brows / TILE_ROWS;   // B = 1M -> exact

    // ---- stage x tile via cp.async: chunk c of row stored at c^(row&7) ----
    auto stage_x = [&](int tile, char* xbase) {
#pragma unroll
        for (int i = 0; i < 8; i++) {
            int idx = tid + i * THREADS;          // 0..1023 chunk slots
            int row = idx >> 3, c = idx & 7;
            uint32_t dst;
            asm("{ .reg .u64 t; cvta.to.shared.u64 t, %1; cvt.u32.u64 %0, t; }"
                : "=r"(dst) : "l"(xbase + row * 128 + ((c ^ (row & 7)) * 16)));
            const float* src = x + (size_t)(tile * TILE_ROWS + row) * 32 + c * 4;
            asm volatile("cp.async.cg.shared.global [%0], [%1], 16;"
                         :: "r"(dst), "l"(src));
        }
    };

    int tile = blockIdx.x;
    int buf = 0;
    if (tile < ntiles) stage_x(tile, sm + SM_X0);
    asm volatile("cp.async.commit_group;" ::: "memory");

    for (; tile < ntiles; tile += gridDim.x) {
        int nxt = tile + gridDim.x;
        if (nxt < ntiles) stage_x(nxt, sm + (buf ? SM_X0 : SM_X1));
        asm volatile("cp.async.commit_group;" ::: "memory");
        asm volatile("cp.async.wait_group 1;" ::: "memory");   // current buf ready
        __syncthreads();

        // ---- x fragments from SMEM (swizzled LDS.128, conflict-free) ----
        uint32_t xa[2][2][4];
        {
            const char* xtile = sm + (buf ? SM_X1 : SM_X0);
#pragma unroll
            for (int s = 0; s < 2; s++) {
                const char* base0 = xtile + (size_t)(wid * ROWS_PER_WARP + 16 * s + r) * 128;
                const char* base8 = base0 + 8 * 128;
                float4 c0 = *reinterpret_cast<const float4*>(base0 + (((2 * m + 0) ^ r) * 16));
                float4 c1 = *reinterpret_cast<const float4*>(base0 + (((2 * m + 1) ^ r) * 16));
                float4 d0 = *reinterpret_cast<const float4*>(base8 + (((2 * m + 0) ^ r) * 16));
                float4 d1 = *reinterpret_cast<const float4*>(base8 + (((2 * m + 1) ^ r) * 16));
                xa[s][0][0] = f22h2(c0.x, c0.y);  xa[s][0][2] = f22h2(c0.z, c0.w);
                xa[s][1][0] = f22h2(c1.x, c1.y);  xa[s][1][2] = f22h2(c1.z, c1.w);
                xa[s][0][1] = f22h2(d0.x, d0.y);  xa[s][0][3] = f22h2(d0.z, d0.w);
                xa[s][1][1] = f22h2(d1.x, d1.y);  xa[s][1][3] = f22h2(d1.z, d1.w);
            }
        }

        // ---- Layer 0: [32,32] x [32,64] ----
        float c[2][8][4];
#pragma unroll
        for (int s = 0; s < 2; s++)
#pragma unroll
            for (int j = 0; j < 8; j++) { c[s][j][0] = c[s][j][1] = c[s][j][2] = c[s][j][3] = 0.f; }
#pragma unroll
        for (int u = 0; u < 2; u++) {
#pragma unroll
            for (int j2 = 0; j2 < 4; j2++) {
                uint4 bb = w0p[((u * 4 + j2) * 32) + lidx];
#pragma unroll
                for (int s = 0; s < 2; s++) {
                    mma16(c[s][2 * j2],     xa[s][u], bb.x, bb.y);
                    mma16(c[s][2 * j2 + 1], xa[s][u], bb.z, bb.w);
                }
            }
        }

        // ReLU (packed hmax2) -> A for layer 1
        uint32_t a[2][4][4];
#pragma unroll
        for (int s = 0; s < 2; s++)
#pragma unroll
            for (int u = 0; u < 4; u++) {
                a[s][u][0] = hmax0(f22h2(c[s][2*u][0],   c[s][2*u][1]));
                a[s][u][1] = hmax0(f22h2(c[s][2*u][2],   c[s][2*u][3]));
                a[s][u][2] = hmax0(f22h2(c[s][2*u+1][0], c[s][2*u+1][1]));
                a[s][u][3] = hmax0(f22h2(c[s][2*u+1][2], c[s][2*u+1][3]));
            }

        // ---- Layer 1: [32,64] x [64,64] (no activation) ----
#pragma unroll
        for (int s = 0; s < 2; s++)
#pragma unroll
            for (int j = 0; j < 8; j++) { c[s][j][0] = c[s][j][1] = c[s][j][2] = c[s][j][3] = 0.f; }
#pragma unroll
        for (int u = 0; u < 4; u++) {
#pragma unroll
            for (int j2 = 0; j2 < 4; j2++) {
                uint4 bb = w1p[((u * 4 + j2) * 32) + lidx];
#pragma unroll
                for (int s = 0; s < 2; s++) {
                    mma16(c[s][2 * j2],     a[s][u], bb.x, bb.y);
                    mma16(c[s][2 * j2 + 1], a[s][u], bb.z, bb.w);
                }
            }
        }
#pragma unroll
        for (int s = 0; s < 2; s++)
#pragma unroll
            for (int u = 0; u < 4; u++) {
                a[s][u][0] = f22h2(c[s][2*u][0],   c[s][2*u][1]);
                a[s][u][1] = f22h2(c[s][2*u][2],   c[s][2*u][3]);
                a[s][u][2] = f22h2(c[s][2*u+1][0], c[s][2*u+1][1]);
                a[s][u][3] = f22h2(c[s][2*u+1][2], c[s][2*u+1][3]);
            }

        // ---- Layer 2: [32,64] x [64,64] (no activation) ----
#pragma unroll
        for (int s = 0; s < 2; s++)
#pragma unroll
            for (int j = 0; j < 8; j++) { c[s][j][0] = c[s][j][1] = c[s][j][2] = c[s][j][3] = 0.f; }
#pragma unroll
        for (int u = 0; u < 4; u++) {
#pragma unroll
            for (int j2 = 0; j2 < 4; j2++) {
                uint4 bb = w2p[((u * 4 + j2) * 32) + lidx];
#pragma unroll
                for (int s = 0; s < 2; s++) {
                    mma16(c[s][2 * j2],     a[s][u], bb.x, bb.y);
                    mma16(c[s][2 * j2 + 1], a[s][u], bb.z, bb.w);
                }
            }
        }
#pragma unroll
        for (int s = 0; s < 2; s++)
#pragma unroll
            for (int u = 0; u < 4; u++) {
                a[s][u][0] = f22h2(c[s][2*u][0],   c[s][2*u][1]);
                a[s][u][1] = f22h2(c[s][2*u][2],   c[s][2*u][3]);
                a[s][u][2] = f22h2(c[s][2*u+1][0], c[s][2*u+1][1]);
                a[s][u][3] = f22h2(c[s][2*u+1][2], c[s][2*u+1][3]);
            }

        // ---- Layer 3: [32,64] x [64,16] (N-permuted weights) ----
        float c3[2][2][4];
#pragma unroll
        for (int s = 0; s < 2; s++)
#pragma unroll
            for (int j = 0; j < 2; j++) { c3[s][j][0] = c3[s][j][1] = c3[s][j][2] = c3[s][j][3] = 0.f; }
#pragma unroll
        for (int u = 0; u < 4; u++) {
            uint4 bb = w3p[(u * 32) + lidx];
#pragma unroll
            for (int s = 0; s < 2; s++) {
                mma16(c3[s][0], a[s][u], bb.x, bb.y);
                mma16(c3[s][1], a[s][u], bb.z, bb.w);
            }
        }

        // ---- Epilogue: ReLU + STG.128 (thread owns 4 adjacent cols) ----
        {
            const int row0 = tile * TILE_ROWS + wid * ROWS_PER_WARP;
#pragma unroll
            for (int s = 0; s < 2; s++) {
                int base = row0 + 16 * s;
                float4 v0, v1;
                v0.x = fmaxf(c3[s][0][0], 0.f); v0.y = fmaxf(c3[s][0][1], 0.f);
                v0.z = fmaxf(c3[s][1][0], 0.f); v0.w = fmaxf(c3[s][1][1], 0.f);
                v1.x = fmaxf(c3[s][0][2], 0.f); v1.y = fmaxf(c3[s][0][3], 0.f);
                v1.z = fmaxf(c3[s][1][2], 0.f); v1.w = fmaxf(c3[s][1][3], 0.f);
                *reinterpret_cast<float4*>(out + (size_t)(base + r) * 16 + 4 * m) = v0;
                *reinterpret_cast<float4*>(out + (size_t)(base + r + 8) * 16 + 4 * m) = v1;
            }
        }

        buf ^= 1;
        __syncthreads();   // all reads of old buf done before next stage into it
    }
}

extern "C" void kernel_launch(void* const* d_in, const int* in_sizes, int n_in,
                              void* d_out, int out_size) {
    const float* x  = (const float*)d_in[0];
    const float* W0 = (const float*)d_in[1];
    const float* W1 = (const float*)d_in[2];
    const float* W2 = (const float*)d_in[3];
    const float* W3 = (const float*)d_in[4];
    float* out = (float*)d_out;
    int Brows = in_sizes[0] / 32;

    cudaFuncSetAttribute(ffmlp_kernel, cudaFuncAttributeMaxDynamicSharedMemorySize, SM_TOTAL);
    int ntiles = Brows / TILE_ROWS;
    int grid = CTAS_PER_SM * 148;
    if (grid > ntiles) grid = ntiles;
    if (grid < 1) grid = 1;
    ffmlp_kernel<<<grid, THREADS, SM_TOTAL>>>(x, W0, W1, W2, W3, out, Brows);
}

// round 12
// speedup vs baseline: 1.0909x; 1.0909x over previous
#include <cuda_runtime.h>
#include <cuda_fp16.h>
#include <cstdint>

// ============================================================
// Fused 4-layer MLP via mma.sync m16n8k16 f16 (fp32 accum).
//   out = relu( ((relu(x@W0^T)) @ W1^T @ W2^T) @ W3^T )
// Each warp carries 2x16 rows through all layers in registers.
// R10: j2-outer / u-inner loop order -> per-n-chunk accumulators
// retire early, packs overlap subsequent MMAs (layer pipelining);
// peak live regs cut (c: 64 -> 16 floats per layer junction).
// ============================================================

#define THREADS 128          // 4 warps/CTA
#define ROWS_PER_WARP 32     // 2 x m16 subtiles
#define TILE_ROWS 128        // 4 warps x 32 rows
#define CTAS_PER_SM 3

// dynamic SMEM layout (bytes)
#define SM_X0   0            // 128 rows x 128B (16 KB)
#define SM_X1   16384
#define SM_W0P  32768        // 256 uint4 (4 KB)
#define SM_W1P  36864        // 512 uint4 (8 KB)
#define SM_W2P  45056        // 512 uint4 (8 KB)
#define SM_W3P  53248        // 128 uint4 (2 KB)
#define SM_TOTAL 55296

static __device__ __forceinline__ uint32_t f22h2(float lo, float hi) {
    __half2 h = __floats2half2_rn(lo, hi);   // lo -> .x (low half)
    return *reinterpret_cast<uint32_t*>(&h);
}

static __device__ __forceinline__ void mma16(float c[4], const uint32_t a[4],
                                             uint32_t b0, uint32_t b1) {
    asm volatile(
        "mma.sync.aligned.m16n8k16.row.col.f32.f16.f16.f32 "
        "{%0,%1,%2,%3}, {%4,%5,%6,%7}, {%8,%9}, {%0,%1,%2,%3};"
        : "+f"(c[0]), "+f"(c[1]), "+f"(c[2]), "+f"(c[3])
        : "r"(a[0]), "r"(a[1]), "r"(a[2]), "r"(a[3]), "r"(b0), "r"(b1));
}

// relu on packed f16x2
static __device__ __forceinline__ uint32_t hmax0(uint32_t v) {
    __half2 h = *reinterpret_cast<__half2*>(&v);
    __half2 z = __float2half2_rn(0.f);
    __half2 r = __hmax2(h, z);
    return *reinterpret_cast<uint32_t*>(&r);
}

__global__ void __launch_bounds__(THREADS, CTAS_PER_SM)
ffmlp_kernel(const float* __restrict__ x,
             const float* __restrict__ W0, const float* __restrict__ W1,
             const float* __restrict__ W2, const float* __restrict__ W3,
             float* __restrict__ out, int Brows) {
    extern __shared__ char sm[];
    uint4* w0p = reinterpret_cast<uint4*>(sm + SM_W0P);
    uint4* w1p = reinterpret_cast<uint4*>(sm + SM_W1P);
    uint4* w2p = reinterpret_cast<uint4*>(sm + SM_W2P);
    uint4* w3p = reinterpret_cast<uint4*>(sm + SM_W3P);

    const int tid = threadIdx.x;

    // ---- stage weights (fp16 pairs) ----
    // L0 with x-load permutation sigma0 (matches xa unpack below)
    for (int i = tid; i < 256; i += THREADS) {
        int u = i >> 7, j2 = (i >> 5) & 3, r = (i >> 2) & 7, m = i & 3;
        int n0 = 16 * j2 + r, n1 = n0 + 8;
        int k = 8 * m + 4 * u;
        const float* p0 = W0 + n0 * 32 + k;
        const float* p1 = W0 + n1 * 32 + k;
        uint4 v;
        v.x = f22h2(__ldg(p0 + 0), __ldg(p0 + 1));
        v.y = f22h2(__ldg(p0 + 2), __ldg(p0 + 3));
        v.z = f22h2(__ldg(p1 + 0), __ldg(p1 + 1));
        v.w = f22h2(__ldg(p1 + 2), __ldg(p1 + 3));
        w0p[i] = v;
    }
    // L1/L2: natural layout (C->A chain needs no permutation for f16 pairs)
    for (int i = tid; i < 512; i += THREADS) {
        int u = i >> 7, j2 = (i >> 5) & 3, r = (i >> 2) & 7, m = i & 3;
        int n0 = 16 * j2 + r, n1 = n0 + 8;
        int k0 = 16 * u + 2 * m;
        uint4 v;
        v.x = f22h2(__ldg(W1 + n0 * 64 + k0),     __ldg(W1 + n0 * 64 + k0 + 1));
        v.y = f22h2(__ldg(W1 + n0 * 64 + k0 + 8), __ldg(W1 + n0 * 64 + k0 + 9));
        v.z = f22h2(__ldg(W1 + n1 * 64 + k0),     __ldg(W1 + n1 * 64 + k0 + 1));
        v.w = f22h2(__ldg(W1 + n1 * 64 + k0 + 8), __ldg(W1 + n1 * 64 + k0 + 9));
        w1p[i] = v;
        v.x = f22h2(__ldg(W2 + n0 * 64 + k0),     __ldg(W2 + n0 * 64 + k0 + 1));
        v.y = f22h2(__ldg(W2 + n0 * 64 + k0 + 8), __ldg(W2 + n0 * 64 + k0 + 9));
        v.z = f22h2(__ldg(W2 + n1 * 64 + k0),     __ldg(W2 + n1 * 64 + k0 + 1));
        v.w = f22h2(__ldg(W2 + n1 * 64 + k0 + 8), __ldg(W2 + n1 * 64 + k0 + 9));
        w2p[i] = v;
    }
    // L3 with N-permutation so each thread's C covers 4 adjacent out cols:
    // block j, frag row r -> physical col 4*(r>>1) + 2*j + (r&1)
    for (int i = tid; i < 128; i += THREADS) {
        int u = i >> 5, r = (i >> 2) & 7, m = i & 3;
        int n0 = 4 * (r >> 1) + (r & 1);   // block 0
        int n1 = n0 + 2;                   // block 1
        int k0 = 16 * u + 2 * m;
        uint4 v;
        v.x = f22h2(__ldg(W3 + n0 * 64 + k0),     __ldg(W3 + n0 * 64 + k0 + 1));
        v.y = f22h2(__ldg(W3 + n0 * 64 + k0 + 8), __ldg(W3 + n0 * 64 + k0 + 9));
        v.z = f22h2(__ldg(W3 + n1 * 64 + k0),     __ldg(W3 + n1 * 64 + k0 + 1));
        v.w = f22h2(__ldg(W3 + n1 * 64 + k0 + 8), __ldg(W3 + n1 * 64 + k0 + 9));
        w3p[i] = v;
    }

    const int wid  = tid >> 5;
    const int lane = tid & 31;
    const int r = lane >> 2;      // group id (row within 8)
    const int m = lane & 3;       // thread-in-group
    const int lidx = r * 4 + m;   // packed (r,m) index

    const int ntiles = Brows / TILE_ROWS;   // B = 1M -> exact

    // ---- stage x tile via cp.async: chunk c of row stored at c^(row&7) ----
    auto stage_x = [&](int tile, char* xbase) {
#pragma unroll
        for (int i = 0; i < 8; i++) {
            int idx = tid + i * THREADS;          // 0..1023 chunk slots
            int row = idx >> 3, c = idx & 7;
            uint32_t dst;
            asm("{ .reg .u64 t; cvta.to.shared.u64 t, %1; cvt.u32.u64 %0, t; }"
                : "=r"(dst) : "l"(xbase + row * 128 + ((c ^ (row & 7)) * 16)));
            const float* src = x + (size_t)(tile * TILE_ROWS + row) * 32 + c * 4;
            asm volatile("cp.async.cg.shared.global [%0], [%1], 16;"
                         :: "r"(dst), "l"(src));
        }
    };

    int tile = blockIdx.x;
    int buf = 0;
    if (tile < ntiles) stage_x(tile, sm + SM_X0);
    asm volatile("cp.async.commit_group;" ::: "memory");

    for (; tile < ntiles; tile += gridDim.x) {
        int nxt = tile + gridDim.x;
        if (nxt < ntiles) stage_x(nxt, sm + (buf ? SM_X0 : SM_X1));
        asm volatile("cp.async.commit_group;" ::: "memory");
        asm volatile("cp.async.wait_group 1;" ::: "memory");   // current buf ready
        __syncthreads();

        // ---- x fragments from SMEM (swizzled LDS.128, conflict-free) ----
        uint32_t xa[2][2][4];
        {
            const char* xtile = sm + (buf ? SM_X1 : SM_X0);
#pragma unroll
            for (int s = 0; s < 2; s++) {
                const char* base0 = xtile + (size_t)(wid * ROWS_PER_WARP + 16 * s + r) * 128;
                const char* base8 = base0 + 8 * 128;
                float4 c0 = *reinterpret_cast<const float4*>(base0 + (((2 * m + 0) ^ r) * 16));
                float4 c1 = *reinterpret_cast<const float4*>(base0 + (((2 * m + 1) ^ r) * 16));
                float4 d0 = *reinterpret_cast<const float4*>(base8 + (((2 * m + 0) ^ r) * 16));
                float4 d1 = *reinterpret_cast<const float4*>(base8 + (((2 * m + 1) ^ r) * 16));
                xa[s][0][0] = f22h2(c0.x, c0.y);  xa[s][0][2] = f22h2(c0.z, c0.w);
                xa[s][1][0] = f22h2(c1.x, c1.y);  xa[s][1][2] = f22h2(c1.z, c1.w);
                xa[s][0][1] = f22h2(d0.x, d0.y);  xa[s][0][3] = f22h2(d0.z, d0.w);
                xa[s][1][1] = f22h2(d1.x, d1.y);  xa[s][1][3] = f22h2(d1.z, d1.w);
            }
        }

        uint32_t a1[2][4][4];   // L0 output fragments (relu'd)
        uint32_t a2[2][4][4];   // L1 output fragments

        // ---- Layer 0: [32,32] x [32,64], j2 outer -> early pack ----
#pragma unroll
        for (int j2 = 0; j2 < 4; j2++) {
            float c[2][2][4];
#pragma unroll
            for (int s = 0; s < 2; s++)
#pragma unroll
                for (int jj = 0; jj < 2; jj++)
                    c[s][jj][0] = c[s][jj][1] = c[s][jj][2] = c[s][jj][3] = 0.f;
#pragma unroll
            for (int u = 0; u < 2; u++) {
                uint4 bb = w0p[((u * 4 + j2) * 32) + lidx];
#pragma unroll
                for (int s = 0; s < 2; s++) {
                    mma16(c[s][0], xa[s][u], bb.x, bb.y);
                    mma16(c[s][1], xa[s][u], bb.z, bb.w);
                }
            }
#pragma unroll
            for (int s = 0; s < 2; s++) {
                a1[s][j2][0] = hmax0(f22h2(c[s][0][0], c[s][0][1]));
                a1[s][j2][1] = hmax0(f22h2(c[s][0][2], c[s][0][3]));
                a1[s][j2][2] = hmax0(f22h2(c[s][1][0], c[s][1][1]));
                a1[s][j2][3] = hmax0(f22h2(c[s][1][2], c[s][1][3]));
            }
        }

        // ---- Layer 1: [32,64] x [64,64], j2 outer -> early pack ----
#pragma unroll
        for (int j2 = 0; j2 < 4; j2++) {
            float c[2][2][4];
#pragma unroll
            for (int s = 0; s < 2; s++)
#pragma unroll
                for (int jj = 0; jj < 2; jj++)
                    c[s][jj][0] = c[s][jj][1] = c[s][jj][2] = c[s][jj][3] = 0.f;
#pragma unroll
            for (int u = 0; u < 4; u++) {
                uint4 bb = w1p[((u * 4 + j2) * 32) + lidx];
#pragma unroll
                for (int s = 0; s < 2; s++) {
                    mma16(c[s][0], a1[s][u], bb.x, bb.y);
                    mma16(c[s][1], a1[s][u], bb.z, bb.w);
                }
            }
#pragma unroll
            for (int s = 0; s < 2; s++) {
                a2[s][j2][0] = f22h2(c[s][0][0], c[s][0][1]);
                a2[s][j2][1] = f22h2(c[s][0][2], c[s][0][3]);
                a2[s][j2][2] = f22h2(c[s][1][0], c[s][1][1]);
                a2[s][j2][3] = f22h2(c[s][1][2], c[s][1][3]);
            }
        }

        // ---- Layer 2: [32,64] x [64,64], j2 outer -> early pack (into a1) ----
#pragma unroll
        for (int j2 = 0; j2 < 4; j2++) {
            float c[2][2][4];
#pragma unroll
            for (int s = 0; s < 2; s++)
#pragma unroll
                for (int jj = 0; jj < 2; jj++)
                    c[s][jj][0] = c[s][jj][1] = c[s][jj][2] = c[s][jj][3] = 0.f;
#pragma unroll
            for (int u = 0; u < 4; u++) {
                uint4 bb = w2p[((u * 4 + j2) * 32) + lidx];
#pragma unroll
                for (int s = 0; s < 2; s++) {
                    mma16(c[s][0], a2[s][u], bb.x, bb.y);
                    mma16(c[s][1], a2[s][u], bb.z, bb.w);
                }
            }
#pragma unroll
            for (int s = 0; s < 2; s++) {
                a1[s][j2][0] = f22h2(c[s][0][0], c[s][0][1]);
                a1[s][j2][1] = f22h2(c[s][0][2], c[s][0][3]);
                a1[s][j2][2] = f22h2(c[s][1][0], c[s][1][1]);
                a1[s][j2][3] = f22h2(c[s][1][2], c[s][1][3]);
            }
        }

        // ---- Layer 3: [32,64] x [64,16] (N-permuted weights) ----
        float c3[2][2][4];
#pragma unroll
        for (int s = 0; s < 2; s++)
#pragma unroll
            for (int j = 0; j < 2; j++) { c3[s][j][0] = c3[s][j][1] = c3[s][j][2] = c3[s][j][3] = 0.f; }
#pragma unroll
        for (int u = 0; u < 4; u++) {
            uint4 bb = w3p[(u * 32) + lidx];
#pragma unroll
            for (int s = 0; s < 2; s++) {
                mma16(c3[s][0], a1[s][u], bb.x, bb.y);
                mma16(c3[s][1], a1[s][u], bb.z, bb.w);
            }
        }

        // ---- Epilogue: ReLU + STG.128 (thread owns 4 adjacent cols) ----
        {
            const int row0 = tile * TILE_ROWS + wid * ROWS_PER_WARP;
#pragma unroll
            for (int s = 0; s < 2; s++) {
                int base = row0 + 16 * s;
                float4 v0, v1;
                v0.x = fmaxf(c3[s][0][0], 0.f); v0.y = fmaxf(c3[s][0][1], 0.f);
                v0.z = fmaxf(c3[s][1][0], 0.f); v0.w = fmaxf(c3[s][1][1], 0.f);
                v1.x = fmaxf(c3[s][0][2], 0.f); v1.y = fmaxf(c3[s][0][3], 0.f);
                v1.z = fmaxf(c3[s][1][2], 0.f); v1.w = fmaxf(c3[s][1][3], 0.f);
                *reinterpret_cast<float4*>(out + (size_t)(base + r) * 16 + 4 * m) = v0;
                *reinterpret_cast<float4*>(out + (size_t)(base + r + 8) * 16 + 4 * m) = v1;
            }
        }

        buf ^= 1;
        __syncthreads();   // all reads of old buf done before next stage into it
    }
}

extern "C" void kernel_launch(void* const* d_in, const int* in_sizes, int n_in,
                              void* d_out, int out_size) {
    const float* x  = (const float*)d_in[0];
    const float* W0 = (const float*)d_in[1];
    const float* W1 = (const float*)d_in[2];
    const float* W2 = (const float*)d_in[3];
    const float* W3 = (const float*)d_in[4];
    float* out = (float*)d_out;
    int Brows = in_sizes[0] / 32;

    cudaFuncSetAttribute(ffmlp_kernel, cudaFuncAttributeMaxDynamicSharedMemorySize, SM_TOTAL);
    int ntiles = Brows / TILE_ROWS;
    int grid = CTAS_PER_SM * 148;
    if (grid > ntiles) grid = ntiles;
    if (grid < 1) grid = 1;
    ffmlp_kernel<<<grid, THREADS, SM_TOTAL>>>(x, W0, W1, W2, W3, out, Brows);
}

// round 13
// speedup vs baseline: 1.0914x; 1.0005x over previous
#include <cuda_runtime.h>
#include <cuda_fp16.h>
#include <cstdint>

// ============================================================
// Fused 4-layer MLP via mma.sync m16n8k16 f16 (fp32 accum).
//   out = relu( ((relu(x@W0^T)) @ W1^T @ W2^T) @ W3^T )
// Each warp carries 2x16 rows through all layers in registers.
// R10: j2-outer / u-inner loop order -> per-n-chunk accumulators
// retire early, packs overlap subsequent MMAs (layer pipelining);
// peak live regs cut (c: 64 -> 16 floats per layer junction).
// ============================================================

#define THREADS 128          // 4 warps/CTA
#define ROWS_PER_WARP 32     // 2 x m16 subtiles
#define TILE_ROWS 128        // 4 warps x 32 rows
#define CTAS_PER_SM 3

// dynamic SMEM layout (bytes)
#define SM_X0   0            // 128 rows x 128B (16 KB)
#define SM_X1   16384
#define SM_W0P  32768        // 256 uint4 (4 KB)
#define SM_W1P  36864        // 512 uint4 (8 KB)
#define SM_W2P  45056        // 512 uint4 (8 KB)
#define SM_W3P  53248        // 128 uint4 (2 KB)
#define SM_TOTAL 55296

static __device__ __forceinline__ uint32_t f22h2(float lo, float hi) {
    __half2 h = __floats2half2_rn(lo, hi);   // lo -> .x (low half)
    return *reinterpret_cast<uint32_t*>(&h);
}

static __device__ __forceinline__ void mma16(float c[4], const uint32_t a[4],
                                             uint32_t b0, uint32_t b1) {
    asm volatile(
        "mma.sync.aligned.m16n8k16.row.col.f32.f16.f16.f32 "
        "{%0,%1,%2,%3}, {%4,%5,%6,%7}, {%8,%9}, {%0,%1,%2,%3};"
        : "+f"(c[0]), "+f"(c[1]), "+f"(c[2]), "+f"(c[3])
        : "r"(a[0]), "r"(a[1]), "r"(a[2]), "r"(a[3]), "r"(b0), "r"(b1));
}

// relu on packed f16x2
static __device__ __forceinline__ uint32_t hmax0(uint32_t v) {
    __half2 h = *reinterpret_cast<__half2*>(&v);
    __half2 z = __float2half2_rn(0.f);
    __half2 r = __hmax2(h, z);
    return *reinterpret_cast<uint32_t*>(&r);
}

__global__ void __launch_bounds__(THREADS, CTAS_PER_SM)
ffmlp_kernel(const float* __restrict__ x,
             const float* __restrict__ W0, const float* __restrict__ W1,
             const float* __restrict__ W2, const float* __restrict__ W3,
             float* __restrict__ out, int Brows) {
    extern __shared__ char sm[];
    uint4* w0p = reinterpret_cast<uint4*>(sm + SM_W0P);
    uint4* w1p = reinterpret_cast<uint4*>(sm + SM_W1P);
    uint4* w2p = reinterpret_cast<uint4*>(sm + SM_W2P);
    uint4* w3p = reinterpret_cast<uint4*>(sm + SM_W3P);

    const int tid = threadIdx.x;

    // ---- stage weights (fp16 pairs) ----
    // L0 with x-load permutation sigma0 (matches xa unpack below)
    for (int i = tid; i < 256; i += THREADS) {
        int u = i >> 7, j2 = (i >> 5) & 3, r = (i >> 2) & 7, m = i & 3;
        int n0 = 16 * j2 + r, n1 = n0 + 8;
        int k = 8 * m + 4 * u;
        const float* p0 = W0 + n0 * 32 + k;
        const float* p1 = W0 + n1 * 32 + k;
        uint4 v;
        v.x = f22h2(__ldg(p0 + 0), __ldg(p0 + 1));
        v.y = f22h2(__ldg(p0 + 2), __ldg(p0 + 3));
        v.z = f22h2(__ldg(p1 + 0), __ldg(p1 + 1));
        v.w = f22h2(__ldg(p1 + 2), __ldg(p1 + 3));
        w0p[i] = v;
    }
    // L1/L2: natural layout (C->A chain needs no permutation for f16 pairs)
    for (int i = tid; i < 512; i += THREADS) {
        int u = i >> 7, j2 = (i >> 5) & 3, r = (i >> 2) & 7, m = i & 3;
        int n0 = 16 * j2 + r, n1 = n0 + 8;
        int k0 = 16 * u + 2 * m;
        uint4 v;
        v.x = f22h2(__ldg(W1 + n0 * 64 + k0),     __ldg(W1 + n0 * 64 + k0 + 1));
        v.y = f22h2(__ldg(W1 + n0 * 64 + k0 + 8), __ldg(W1 + n0 * 64 + k0 + 9));
        v.z = f22h2(__ldg(W1 + n1 * 64 + k0),     __ldg(W1 + n1 * 64 + k0 + 1));
        v.w = f22h2(__ldg(W1 + n1 * 64 + k0 + 8), __ldg(W1 + n1 * 64 + k0 + 9));
        w1p[i] = v;
        v.x = f22h2(__ldg(W2 + n0 * 64 + k0),     __ldg(W2 + n0 * 64 + k0 + 1));
        v.y = f22h2(__ldg(W2 + n0 * 64 + k0 + 8), __ldg(W2 + n0 * 64 + k0 + 9));
        v.z = f22h2(__ldg(W2 + n1 * 64 + k0),     __ldg(W2 + n1 * 64 + k0 + 1));
        v.w = f22h2(__ldg(W2 + n1 * 64 + k0 + 8), __ldg(W2 + n1 * 64 + k0 + 9));
        w2p[i] = v;
    }
    // L3 with N-permutation so each thread's C covers 4 adjacent out cols:
    // block j, frag row r -> physical col 4*(r>>1) + 2*j + (r&1)
    for (int i = tid; i < 128; i += THREADS) {
        int u = i >> 5, r = (i >> 2) & 7, m = i & 3;
        int n0 = 4 * (r >> 1) + (r & 1);   // block 0
        int n1 = n0 + 2;                   // block 1
        int k0 = 16 * u + 2 * m;
        uint4 v;
        v.x = f22h2(__ldg(W3 + n0 * 64 + k0),     __ldg(W3 + n0 * 64 + k0 + 1));
        v.y = f22h2(__ldg(W3 + n0 * 64 + k0 + 8), __ldg(W3 + n0 * 64 + k0 + 9));
        v.z = f22h2(__ldg(W3 + n1 * 64 + k0),     __ldg(W3 + n1 * 64 + k0 + 1));
        v.w = f22h2(__ldg(W3 + n1 * 64 + k0 + 8), __ldg(W3 + n1 * 64 + k0 + 9));
        w3p[i] = v;
    }

    const int wid  = tid >> 5;
    const int lane = tid & 31;
    const int r = lane >> 2;      // group id (row within 8)
    const int m = lane & 3;       // thread-in-group
    const int lidx = r * 4 + m;   // packed (r,m) index

    const int ntiles = Brows / TILE_ROWS;   // B = 1M -> exact

    // ---- stage x tile via cp.async: chunk c of row stored at c^(row&7) ----
    auto stage_x = [&](int tile, char* xbase) {
#pragma unroll
        for (int i = 0; i < 8; i++) {
            int idx = tid + i * THREADS;          // 0..1023 chunk slots
            int row = idx >> 3, c = idx & 7;
            uint32_t dst;
            asm("{ .reg .u64 t; cvta.to.shared.u64 t, %1; cvt.u32.u64 %0, t; }"
                : "=r"(dst) : "l"(xbase + row * 128 + ((c ^ (row & 7)) * 16)));
            const float* src = x + (size_t)(tile * TILE_ROWS + row) * 32 + c * 4;
            asm volatile("cp.async.cg.shared.global [%0], [%1], 16;"
                         :: "r"(dst), "l"(src));
        }
    };

    int tile = blockIdx.x;
    int buf = 0;
    if (tile < ntiles) stage_x(tile, sm + SM_X0);
    asm volatile("cp.async.commit_group;" ::: "memory");

    for (; tile < ntiles; tile += gridDim.x) {
        int nxt = tile + gridDim.x;
        if (nxt < ntiles) stage_x(nxt, sm + (buf ? SM_X0 : SM_X1));
        asm volatile("cp.async.commit_group;" ::: "memory");
        asm volatile("cp.async.wait_group 1;" ::: "memory");   // current buf ready
        __syncthreads();

        // ---- x fragments from SMEM (swizzled LDS.128, conflict-free) ----
        uint32_t xa[2][2][4];
        {
            const char* xtile = sm + (buf ? SM_X1 : SM_X0);
#pragma unroll
            for (int s = 0; s < 2; s++) {
                const char* base0 = xtile + (size_t)(wid * ROWS_PER_WARP + 16 * s + r) * 128;
                const char* base8 = base0 + 8 * 128;
                float4 c0 = *reinterpret_cast<const float4*>(base0 + (((2 * m + 0) ^ r) * 16));
                float4 c1 = *reinterpret_cast<const float4*>(base0 + (((2 * m + 1) ^ r) * 16));
                float4 d0 = *reinterpret_cast<const float4*>(base8 + (((2 * m + 0) ^ r) * 16));
                float4 d1 = *reinterpret_cast<const float4*>(base8 + (((2 * m + 1) ^ r) * 16));
                xa[s][0][0] = f22h2(c0.x, c0.y);  xa[s][0][2] = f22h2(c0.z, c0.w);
                xa[s][1][0] = f22h2(c1.x, c1.y);  xa[s][1][2] = f22h2(c1.z, c1.w);
                xa[s][0][1] = f22h2(d0.x, d0.y);  xa[s][0][3] = f22h2(d0.z, d0.w);
                xa[s][1][1] = f22h2(d1.x, d1.y);  xa[s][1][3] = f22h2(d1.z, d1.w);
            }
        }

        uint32_t a1[2][4][4];   // L0 output fragments (relu'd)
        uint32_t a2[2][4][4];   // L1 output fragments

        // ---- Layer 0: [32,32] x [32,64], j2 outer -> early pack ----
#pragma unroll
        for (int j2 = 0; j2 < 4; j2++) {
            float c[2][2][4];
#pragma unroll
            for (int s = 0; s < 2; s++)
#pragma unroll
                for (int jj = 0; jj < 2; jj++)
                    c[s][jj][0] = c[s][jj][1] = c[s][jj][2] = c[s][jj][3] = 0.f;
#pragma unroll
            for (int u = 0; u < 2; u++) {
                uint4 bb = w0p[((u * 4 + j2) * 32) + lidx];
#pragma unroll
                for (int s = 0; s < 2; s++) {
                    mma16(c[s][0], xa[s][u], bb.x, bb.y);
                    mma16(c[s][1], xa[s][u], bb.z, bb.w);
                }
            }
#pragma unroll
            for (int s = 0; s < 2; s++) {
                a1[s][j2][0] = hmax0(f22h2(c[s][0][0], c[s][0][1]));
                a1[s][j2][1] = hmax0(f22h2(c[s][0][2], c[s][0][3]));
                a1[s][j2][2] = hmax0(f22h2(c[s][1][0], c[s][1][1]));
                a1[s][j2][3] = hmax0(f22h2(c[s][1][2], c[s][1][3]));
            }
        }

        // ---- Layer 1: [32,64] x [64,64], j2 outer -> early pack ----
#pragma unroll
        for (int j2 = 0; j2 < 4; j2++) {
            float c[2][2][4];
#pragma unroll
            for (int s = 0; s < 2; s++)
#pragma unroll
                for (int jj = 0; jj < 2; jj++)
                    c[s][jj][0] = c[s][jj][1] = c[s][jj][2] = c[s][jj][3] = 0.f;
#pragma unroll
            for (int u = 0; u < 4; u++) {
                uint4 bb = w1p[((u * 4 + j2) * 32) + lidx];
#pragma unroll
                for (int s = 0; s < 2; s++) {
                    mma16(c[s][0], a1[s][u], bb.x, bb.y);
                    mma16(c[s][1], a1[s][u], bb.z, bb.w);
                }
            }
#pragma unroll
            for (int s = 0; s < 2; s++) {
                a2[s][j2][0] = f22h2(c[s][0][0], c[s][0][1]);
                a2[s][j2][1] = f22h2(c[s][0][2], c[s][0][3]);
                a2[s][j2][2] = f22h2(c[s][1][0], c[s][1][1]);
                a2[s][j2][3] = f22h2(c[s][1][2], c[s][1][3]);
            }
        }

        // ---- Layer 2: [32,64] x [64,64], j2 outer -> early pack (into a1) ----
#pragma unroll
        for (int j2 = 0; j2 < 4; j2++) {
            float c[2][2][4];
#pragma unroll
            for (int s = 0; s < 2; s++)
#pragma unroll
                for (int jj = 0; jj < 2; jj++)
                    c[s][jj][0] = c[s][jj][1] = c[s][jj][2] = c[s][jj][3] = 0.f;
#pragma unroll
            for (int u = 0; u < 4; u++) {
                uint4 bb = w2p[((u * 4 + j2) * 32) + lidx];
#pragma unroll
                for (int s = 0; s < 2; s++) {
                    mma16(c[s][0], a2[s][u], bb.x, bb.y);
                    mma16(c[s][1], a2[s][u], bb.z, bb.w);
                }
            }
#pragma unroll
            for (int s = 0; s < 2; s++) {
                a1[s][j2][0] = f22h2(c[s][0][0], c[s][0][1]);
                a1[s][j2][1] = f22h2(c[s][0][2], c[s][0][3]);
                a1[s][j2][2] = f22h2(c[s][1][0], c[s][1][1]);
                a1[s][j2][3] = f22h2(c[s][1][2], c[s][1][3]);
            }
        }

        // ---- Layer 3: [32,64] x [64,16] (N-permuted weights) ----
        float c3[2][2][4];
#pragma unroll
        for (int s = 0; s < 2; s++)
#pragma unroll
            for (int j = 0; j < 2; j++) { c3[s][j][0] = c3[s][j][1] = c3[s][j][2] = c3[s][j][3] = 0.f; }
#pragma unroll
        for (int u = 0; u < 4; u++) {
            uint4 bb = w3p[(u * 32) + lidx];
#pragma unroll
            for (int s = 0; s < 2; s++) {
                mma16(c3[s][0], a1[s][u], bb.x, bb.y);
                mma16(c3[s][1], a1[s][u], bb.z, bb.w);
            }
        }

        // ---- Epilogue: ReLU + STG.128 (thread owns 4 adjacent cols) ----
        {
            const int row0 = tile * TILE_ROWS + wid * ROWS_PER_WARP;
#pragma unroll
            for (int s = 0; s < 2; s++) {
                int base = row0 + 16 * s;
                float4 v0, v1;
                v0.x = fmaxf(c3[s][0][0], 0.f); v0.y = fmaxf(c3[s][0][1], 0.f);
                v0.z = fmaxf(c3[s][1][0], 0.f); v0.w = fmaxf(c3[s][1][1], 0.f);
                v1.x = fmaxf(c3[s][0][2], 0.f); v1.y = fmaxf(c3[s][0][3], 0.f);
                v1.z = fmaxf(c3[s][1][2], 0.f); v1.w = fmaxf(c3[s][1][3], 0.f);
                *reinterpret_cast<float4*>(out + (size_t)(base + r) * 16 + 4 * m) = v0;
                *reinterpret_cast<float4*>(out + (size_t)(base + r + 8) * 16 + 4 * m) = v1;
            }
        }

        buf ^= 1;
        __syncthreads();   // all reads of old buf done before next stage into it
    }
}

extern "C" void kernel_launch(void* const* d_in, const int* in_sizes, int n_in,
                              void* d_out, int out_size) {
    const float* x  = (const float*)d_in[0];
    const float* W0 = (const float*)d_in[1];
    const float* W1 = (const float*)d_in[2];
    const float* W2 = (const float*)d_in[3];
    const float* W3 = (const float*)d_in[4];
    float* out = (float*)d_out;
    int Brows = in_sizes[0] / 32;

    cudaFuncSetAttribute(ffmlp_kernel, cudaFuncAttributeMaxDynamicSharedMemorySize, SM_TOTAL);
    int ntiles = Brows / TILE_ROWS;
    int grid = CTAS_PER_SM * 148;
    if (grid > ntiles) grid = ntiles;
    if (grid < 1) grid = 1;
    ffmlp_kernel<<<grid, THREADS, SM_TOTAL>>>(x, W0, W1, W2, W3, out, Brows);
}